// round 15
// baseline (speedup 1.0000x reference)
#include <cuda_runtime.h>
#include <cuda_fp16.h>
#include <cstdint>
#include <cstddef>

// ---------------- problem constants ----------------
#define IN_DIM   1024
#define OUT_DIM  1024
#define NKNOT    15
#define GK       11
#define TOKENS   8192

// ---------------- sparse layout ----------------
// Per input channel: 12 dense-equivalent K slots, 3 groups of 4:
//   G0 = {spline2, spline6, spline10, SILU}
//   G1 = {spline3, spline4, spline7, spline8}
//   G2 = {spline0, spline1, spline5, spline9}
// Cubic B-spline nonzeros occupy <=4 consecutive slots -> every group is 2:4 sparse.
#define KDE      12288                 // dense-equivalent K (12 * 1024), silu folded in

// ---------------- GEMM config (8 channels per stage, fused A build) ----------------
#define TILE_M   128
#define TILE_N   128
#define KSPLIT   4
#define SEG_CH   256                   // channels per K-split segment
#define NITER_S  32                    // 256 channels / 8 per stage
#define STAGES   3
#define LDSA     112                   // bytes per A smem row (48 halves = 96B + pad)
#define LDSB     208                   // bytes per B smem row (96 halves = 192B + pad)
#define A_BYTES  (TILE_M * LDSA)       // 14336
#define B_BYTES  (TILE_N * LDSB)       // 26624
#define M_BYTES  (TILE_M * 16)         // 2048 (3 meta words + pad per row)
#define STG      (A_BYTES + B_BYTES + M_BYTES)   // 43008
#define SMEM_TOT (STAGES * STG)        // 129024
#define BOFF_REL A_BYTES
#define MOFF_REL (A_BYTES + B_BYTES)

// ---------------- scratch ----------------
__device__ __align__(1024) __half W2_buf[(size_t)OUT_DIM * KDE];               // ~25 MB
__device__ __align__(1024) __half Y4h_buf[(size_t)KSPLIT * TOKENS * OUT_DIM];  // 64 MB

// slot map: dense pos p (0..11) -> spline slot, -2 = silu  (W build)
__device__ __constant__ int PERM2[12] = {2, 6, 10, -2,  3, 4, 7, 8,  0, 1, 5, 9};

// Precomputed sparse-encode LUTs, indexed by jc = (0<=j0<=13) ? j0 : 14.
__device__ __constant__ uint16_t CODE_LUT[16] = {
    0x44E, 0x44E, 0x44C, 0x44C, 0x44C, 0x94C, 0x94D, 0x99D,
    0x9ED, 0xEED, 0xEEE, 0xEEE, 0xE4E, 0x44E, 0x44E, 0x44E};
// SEL_LUT: six 4-bit selectors (g0q0,g0q1,g1q0,g1q1,g2q0,g2q1), values:
// 0..3 -> v0..v3, 4 -> silu, 5 -> zero.
__device__ __constant__ uint32_t SEL_LUT[16] = {
    0x535545, 0x325545, 0x215543, 0x105342, 0x053241, 0x352140, 0x251043, 0x153042,
    0x053241, 0x352140, 0x251043, 0x150542, 0x055541, 0x555540, 0x555545, 0x555545};

// ---------------- PTX helpers ----------------
__device__ __forceinline__ uint32_t smem_u32(const void* p) {
    uint32_t a;
    asm("{ .reg .u64 t; cvta.to.shared.u64 t, %1; cvt.u32.u64 %0, t; }" : "=r"(a) : "l"(p));
    return a;
}
__device__ __forceinline__ void cp_async16(uint32_t dst, const void* src) {
    asm volatile("cp.async.cg.shared.global [%0], [%1], 16;" :: "r"(dst), "l"(src) : "memory");
}
__device__ __forceinline__ void ldmatrix_x4(uint32_t* r, uint32_t addr) {
    asm volatile("ldmatrix.sync.aligned.m8n8.x4.shared.b16 {%0,%1,%2,%3}, [%4];"
                 : "=r"(r[0]), "=r"(r[1]), "=r"(r[2]), "=r"(r[3]) : "r"(addr));
}
__device__ __forceinline__ uint4 lds_v4(uint32_t addr) {
    uint4 v;
    asm volatile("ld.shared.v4.b32 {%0,%1,%2,%3}, [%4];"
                 : "=r"(v.x), "=r"(v.y), "=r"(v.z), "=r"(v.w) : "r"(addr));
    return v;
}
__device__ __forceinline__ void mma_sp(float* c, const uint32_t* a, const uint32_t* b, uint32_t e) {
    asm volatile("mma.sp::ordered_metadata.sync.aligned.m16n8k32.row.col.f32.f16.f16.f32 "
                 "{%0,%1,%2,%3}, {%4,%5,%6,%7}, {%8,%9,%10,%11}, {%0,%1,%2,%3}, %12, 0x0;"
                 : "+f"(c[0]), "+f"(c[1]), "+f"(c[2]), "+f"(c[3])
                 : "r"(a[0]), "r"(a[1]), "r"(a[2]), "r"(a[3]),
                   "r"(b[0]), "r"(b[1]), "r"(b[2]), "r"(b[3]), "r"(e));
}
__device__ __forceinline__ float pick6(uint32_t idx, float v0, float v1, float v2,
                                       float v3, float sl) {
    // idx: 0..3 -> v0..v3, 4 -> sl, 5 -> 0
    return (idx & 4u) ? ((idx & 1u) ? 0.0f : sl)
         : ((idx & 2u) ? ((idx & 1u) ? v3 : v2)
                       : ((idx & 1u) ? v1 : v0));
}

// Fused A build: one stage = 8 channels x 128 rows. 2 threads per row
// (h = t&1 handles channels 4h..4h+3). Writes 48 compressed halves/row and
// 3 metadata words/row (16B stride) to SMEM. Bit-identical to R13 encode.
__device__ __forceinline__ void build_stage(uint32_t abase, uint32_t mbase,
                                            const float* __restrict__ xbase,
                                            int it, int t, float g0, float inv_h) {
    const int r = t >> 1, h = t & 1;
    const float4 x4 = *reinterpret_cast<const float4*>(
        xbase + (size_t)r * IN_DIM + it * 8 + h * 4);
    const float xs[4] = {x4.x, x4.y, x4.z, x4.w};
    unsigned long long pk = 0;
    const uint32_t vbase = abase + (uint32_t)(r * LDSA + h * 48);
#pragma unroll
    for (int c = 0; c < 4; ++c) {
        const float xv  = xs[c];
        const float pos = (xv - g0) * inv_h;
        const int   j0  = (int)floorf(pos);
        const uint32_t jc = ((unsigned)j0 <= 13u) ? (uint32_t)j0 : 14u;
        const float u  = pos - (float)j0;
        const float u2 = u * u, u3 = u2 * u, om = 1.0f - u;
        const float c6 = 1.0f / 6.0f;
        const float v0 = om * om * om * c6;                    // slot j0-3
        const float v1 = (4.0f - 6.0f * u2 + 3.0f * u3) * c6;  // slot j0-2
        const float v2 = (1.0f + 3.0f * (u + u2 - u3)) * c6;   // slot j0-1
        const float v3 = u3 * c6;                              // slot j0
        const float sl = __fdividef(xv, 1.0f + __expf(-xv));   // silu
        const uint32_t sel = SEL_LUT[jc];
        pk |= (unsigned long long)CODE_LUT[jc] << (12 * c);
#pragma unroll
        for (int g = 0; g < 3; ++g) {
            const float q0 = pick6((sel >> (8 * g))     & 7u, v0, v1, v2, v3, sl);
            const float q1 = pick6((sel >> (8 * g + 4)) & 7u, v0, v1, v2, v3, sl);
            const __half2 hh = __floats2half2_rn(q0, q1);
            asm volatile("st.shared.b32 [%0], %1;"
                         :: "r"(vbase + (uint32_t)(c * 12 + g * 4)),
                            "r"(*reinterpret_cast<const uint32_t*>(&hh)) : "memory");
        }
    }
    // merge the two 48-bit code packs of this row into 3 words (96-bit stream)
    const unsigned long long other = __shfl_xor_sync(0xFFFFFFFFu, pk, 1);
    if (h == 0) {
        const uint32_t w0 = (uint32_t)pk;
        const uint32_t w1 = (uint32_t)(pk >> 32) | (uint32_t)(other << 16);
        const uint32_t w2 = (uint32_t)(other >> 16);
        asm volatile("st.shared.v4.b32 [%0], {%1,%2,%3,%4};"
                     :: "r"(mbase + (uint32_t)(r * 16)), "r"(w0), "r"(w1), "r"(w2), "r"(0u)
                     : "memory");
    }
}

// ================= kernel 1: W = permuted [coeff*ss | silu-slot sb] (fp16) =================
__global__ void __launch_bounds__(256) build_W_kernel(const float* __restrict__ coeff,
                                                      const float* __restrict__ sb,
                                                      const float* __restrict__ ss) {
    const int o = blockIdx.x, t = threadIdx.x;
    const float s = ss[0];
    __half* w = W2_buf + (size_t)o * KDE;
    for (int d = t; d < KDE; d += 256) {
        const int i = d / 12, p = d % 12;
        const int slt = PERM2[p];
        float v;
        if (slt >= 0) v = coeff[((size_t)o * IN_DIM + i) * GK + slt] * s;
        else          v = sb[(size_t)o * IN_DIM + i];          // silu slot
        w[d] = __float2half(v);
    }
}

// ================= kernel 2: fused build + sparse HMMA GEMM, split-K=4 =================
__global__ void __launch_bounds__(256) kan_spgemm_kernel(const float* __restrict__ x,
                                                         const float* __restrict__ grid) {
    extern __shared__ char smem[];
    const uint32_t sbase = smem_u32(smem);
    const int t    = threadIdx.x;
    const int lane = t & 31;
    const int wid  = t >> 5;
    const int m0   = blockIdx.y * TILE_M;
    const int n0   = blockIdx.x * TILE_N;
    const int chg  = blockIdx.z * SEG_CH;   // channel base of this K segment
    const int wm   = (wid >> 2) * 64;
    const int wn   = (wid & 3) * 32;

    const float g0    = grid[0];
    const float inv_h = 1.0f / (grid[1] - grid[0]);
    const float*  xbase = x + (size_t)m0 * IN_DIM + chg;
    const __half* Bg    = W2_buf + (size_t)n0 * KDE + (size_t)chg * 12;

    // B cp.async assignment: 1536 16B-chunks/stage -> 6 per thread
    int rB[6], cB[6];
#pragma unroll
    for (int qq = 0; qq < 6; ++qq) {
        const int c = t + 256 * qq;
        rB[qq] = c / 12;
        cB[qq] = c % 12;
    }

    float acc[4][4][4];
#pragma unroll
    for (int i = 0; i < 4; i++)
#pragma unroll
        for (int j = 0; j < 4; j++)
#pragma unroll
            for (int qv = 0; qv < 4; qv++) acc[i][j][qv] = 0.0f;

    // ---- prologue: B(0), B(1) in flight; A(0), A(1) built ----
#pragma unroll
    for (int s = 0; s < 2; ++s) {
        const uint32_t nb = sbase + s * STG;
#pragma unroll
        for (int qq = 0; qq < 6; ++qq)
            cp_async16(nb + BOFF_REL + (uint32_t)(rB[qq] * LDSB + cB[qq] * 16),
                       Bg + (size_t)rB[qq] * KDE + s * 96 + cB[qq] * 8);
        asm volatile("cp.async.commit_group;" ::: "memory");
    }
    build_stage(sbase,       sbase + MOFF_REL,       xbase, 0, t, g0, inv_h);
    build_stage(sbase + STG, sbase + STG + MOFF_REL, xbase, 1, t, g0, inv_h);

    const int q   = lane >> 2;
    const int msh = (lane & 1) * 16;

    // ---- main loop ----
    for (int it = 0; it < NITER_S; ++it) {
        if (it == NITER_S - 1) asm volatile("cp.async.wait_group 0;" ::: "memory");
        else                   asm volatile("cp.async.wait_group 1;" ::: "memory");
        __syncthreads();

        const int nit = it + 2;
        if (nit < NITER_S) {
            const uint32_t nb = sbase + (nit % STAGES) * STG;
#pragma unroll
            for (int qq = 0; qq < 6; ++qq)
                cp_async16(nb + BOFF_REL + (uint32_t)(rB[qq] * LDSB + cB[qq] * 16),
                           Bg + (size_t)rB[qq] * KDE + (size_t)nit * 96 + cB[qq] * 8);
            build_stage(nb, nb + MOFF_REL, xbase, nit, t, g0, inv_h);
        }
        asm volatile("cp.async.commit_group;" ::: "memory");

        // compute stage it
        const uint32_t ba   = sbase + (it % STAGES) * STG;
        const uint32_t boff = ba + BOFF_REL;
        const uint32_t moff = ba + MOFF_REL;

        // metadata (L2 distribution): lane 4q+s (s=lane&1) supplies, for k-half s:
        // low 16 bits = row q, high 16 bits = row q+8.
        uint32_t ek[4][3];
#pragma unroll
        for (int mt = 0; mt < 4; ++mt) {
            const uint4 lo = lds_v4(moff + (uint32_t)((wm + mt * 16 + q) * 16));
            const uint4 hi = lds_v4(moff + (uint32_t)((wm + mt * 16 + q + 8) * 16));
            ek[mt][0] = ((lo.x >> msh) & 0xFFFFu) | (((hi.x >> msh) & 0xFFFFu) << 16);
            ek[mt][1] = ((lo.y >> msh) & 0xFFFFu) | (((hi.y >> msh) & 0xFFFFu) << 16);
            ek[mt][2] = ((lo.z >> msh) & 0xFFFFu) | (((hi.z >> msh) & 0xFFFFu) << 16);
        }
#pragma unroll
        for (int ks = 0; ks < 3; ++ks) {
            uint32_t afr[4][4], bfr[4][4];
#pragma unroll
            for (int mt = 0; mt < 4; ++mt)
                ldmatrix_x4(afr[mt],
                    ba + (uint32_t)((wm + mt * 16 + (lane & 15)) * LDSA
                                    + ks * 32 + (lane >> 4) * 16));
#pragma unroll
            for (int nt = 0; nt < 4; ++nt)
                ldmatrix_x4(bfr[nt],
                    boff + (uint32_t)((wn + nt * 8 + (lane & 7)) * LDSB
                                      + ks * 64 + ((lane >> 3) & 3) * 16));
#pragma unroll
            for (int mt = 0; mt < 4; ++mt)
#pragma unroll
                for (int nt = 0; nt < 4; ++nt)
                    mma_sp(acc[mt][nt], afr[mt], bfr[nt], ek[mt][ks]);
        }
    }

    // ---- epilogue: fp16 partials -> Y4h ----
    __half* yp = Y4h_buf + (size_t)blockIdx.z * TOKENS * OUT_DIM;
    const int crow = lane >> 2, ccol = (lane & 3) * 2;
#pragma unroll
    for (int mt = 0; mt < 4; ++mt) {
        const int rbase = m0 + wm + mt * 16 + crow;
        __half* y0 = yp + (size_t)rbase * OUT_DIM + n0 + wn + ccol;
        __half* y1 = yp + (size_t)(rbase + 8) * OUT_DIM + n0 + wn + ccol;
#pragma unroll
        for (int nt = 0; nt < 4; ++nt) {
            *reinterpret_cast<__half2*>(y0 + nt * 8) =
                __floats2half2_rn(acc[mt][nt][0], acc[mt][nt][1]);
            *reinterpret_cast<__half2*>(y1 + nt * 8) =
                __floats2half2_rn(acc[mt][nt][2], acc[mt][nt][3]);
        }
    }
}

// ================= kernel 3: y = sum of 4 fp16 partials (fp32 accum) =================
__global__ void __launch_bounds__(256) reduce_kernel(float* __restrict__ y) {
    const size_t n8 = (size_t)TOKENS * OUT_DIM / 8;       // uint4 chunks (8 halves)
    const size_t i  = (size_t)blockIdx.x * 256 + threadIdx.x;
    const uint4* p = reinterpret_cast<const uint4*>(Y4h_buf);
    uint4 a = p[i], b = p[i + n8], c = p[i + 2 * n8], d = p[i + 3 * n8];
    float out[8];
#pragma unroll
    for (int j = 0; j < 4; ++j) {
        const float2 fa = __half22float2(reinterpret_cast<const __half2*>(&a)[j]);
        const float2 fb = __half22float2(reinterpret_cast<const __half2*>(&b)[j]);
        const float2 fc = __half22float2(reinterpret_cast<const __half2*>(&c)[j]);
        const float2 fd = __half22float2(reinterpret_cast<const __half2*>(&d)[j]);
        out[2 * j]     = (fa.x + fb.x) + (fc.x + fd.x);
        out[2 * j + 1] = (fa.y + fb.y) + (fc.y + fd.y);
    }
    float4* yo = reinterpret_cast<float4*>(y) + 2 * i;
    yo[0] = make_float4(out[0], out[1], out[2], out[3]);
    yo[1] = make_float4(out[4], out[5], out[6], out[7]);
}

// ================= host =================
extern "C" void kernel_launch(void* const* d_in, const int* in_sizes, int n_in,
                              void* d_out, int out_size) {
    const float* x     = (const float*)d_in[0];
    const float* grid  = (const float*)d_in[1];
    const float* coeff = (const float*)d_in[2];
    const float* sbase = (const float*)d_in[3];
    const float* sspl  = (const float*)d_in[4];
    float* y = (float*)d_out;

    cudaFuncSetAttribute(kan_spgemm_kernel,
                         cudaFuncAttributeMaxDynamicSharedMemorySize, SMEM_TOT);

    build_W_kernel<<<OUT_DIM, 256>>>(coeff, sbase, sspl);
    kan_spgemm_kernel<<<dim3(OUT_DIM / TILE_N, TOKENS / TILE_M, KSPLIT), 256, SMEM_TOT>>>(x, grid);
    reduce_kernel<<<(TOKENS * OUT_DIM / 8) / 256, 256>>>(y);
}

// round 16
// speedup vs baseline: 1.7444x; 1.7444x over previous
#include <cuda_runtime.h>
#include <cuda_fp16.h>
#include <cstdint>
#include <cstddef>

// ---------------- problem constants ----------------
#define IN_DIM   1024
#define OUT_DIM  1024
#define NKNOT    15
#define GK       11
#define TOKENS   8192

// ---------------- sparse layout ----------------
// Per input channel: 12 dense-equivalent K slots, 3 groups of 4:
//   G0 = {spline2, spline6, spline10, SILU}
//   G1 = {spline3, spline4, spline7, spline8}
//   G2 = {spline0, spline1, spline5, spline9}
// Cubic B-spline nonzeros occupy <=4 consecutive slots -> every group is 2:4 sparse.
#define KDE      12288                 // dense-equivalent K (12 * 1024), silu folded in
#define CKC      6144                  // compressed halves per A row
#define METAW    384                   // metadata uint32 per A row (KDE/32)

// ---------------- GEMM config ----------------
#define TILE_M   128
#define TILE_N   128
#define KSPLIT   4
#define SEG_DE   (KDE / KSPLIT)        // 3072
#define SEG_C    (SEG_DE / 2)          // 1536
#define SEG_MW   (SEG_DE / 32)         // 96
#define BKD      64                    // dense-equiv K per stage (2 x k32)
#define BKC      32                    // compressed halves per stage
#define NITER_S  (SEG_DE / BKD)        // 48
#define STAGES   3
#define LDSA     80                    // bytes per A smem row (32 halves + pad)
#define LDSB     144                   // bytes per B smem row (64 halves + pad)
#define A_BYTES  (TILE_M * LDSA)       // 10240
#define B_BYTES  (TILE_N * LDSB)       // 18432
#define M_BYTES  (TILE_M * 8)          // 1024
#define STG      (A_BYTES + B_BYTES + M_BYTES)   // 29696
#define SMEM_TOT (STAGES * STG)        // 89088

// ---------------- scratch ----------------
__device__ __align__(1024) __half   A_sp[(size_t)TOKENS * CKC];                  // ~100 MB
__device__ __align__(1024) __half   W2_buf[(size_t)OUT_DIM * KDE];               // ~25 MB
__device__ __align__(1024) uint32_t Meta_buf[(size_t)TOKENS * METAW];            // ~12.6 MB
__device__ __align__(1024) __half   Y4h_buf[(size_t)KSPLIT * TOKENS * OUT_DIM];  // 64 MB

// slot map: dense pos p (0..11) -> spline slot, -2 = silu  (used by W build only)
__device__ __constant__ int PERM2[12] = {2, 6, 10, -2,  3, 4, 7, 8,  0, 1, 5, 9};

// Precomputed sparse-encode LUTs, indexed by jc = (0<=j0<=13) ? j0 : 14.
__device__ __constant__ uint16_t CODE_LUT[16] = {
    0x44E, 0x44E, 0x44C, 0x44C, 0x44C, 0x94C, 0x94D, 0x99D,
    0x9ED, 0xEED, 0xEEE, 0xEEE, 0xE4E, 0x44E, 0x44E, 0x44E};
// SEL_LUT: six 4-bit selectors (g0q0,g0q1,g1q0,g1q1,g2q0,g2q1), values:
// 0..3 -> v0..v3, 4 -> silu, 5 -> zero.
__device__ __constant__ uint32_t SEL_LUT[16] = {
    0x535545, 0x325545, 0x215543, 0x105342, 0x053241, 0x352140, 0x251043, 0x153042,
    0x053241, 0x352140, 0x251043, 0x150542, 0x055541, 0x555540, 0x555545, 0x555545};

// ---------------- PTX helpers ----------------
__device__ __forceinline__ uint32_t smem_u32(const void* p) {
    uint32_t a;
    asm("{ .reg .u64 t; cvta.to.shared.u64 t, %1; cvt.u32.u64 %0, t; }" : "=r"(a) : "l"(p));
    return a;
}
__device__ __forceinline__ void cp_async16(uint32_t dst, const void* src) {
    asm volatile("cp.async.cg.shared.global [%0], [%1], 16;" :: "r"(dst), "l"(src) : "memory");
}
__device__ __forceinline__ void cp_async8(uint32_t dst, const void* src) {
    asm volatile("cp.async.ca.shared.global [%0], [%1], 8;" :: "r"(dst), "l"(src) : "memory");
}
__device__ __forceinline__ void ldmatrix_x4(uint32_t* r, uint32_t addr) {
    asm volatile("ldmatrix.sync.aligned.m8n8.x4.shared.b16 {%0,%1,%2,%3}, [%4];"
                 : "=r"(r[0]), "=r"(r[1]), "=r"(r[2]), "=r"(r[3]) : "r"(addr));
}
__device__ __forceinline__ void mma_sp(float* c, const uint32_t* a, const uint32_t* b, uint32_t e) {
    asm volatile("mma.sp::ordered_metadata.sync.aligned.m16n8k32.row.col.f32.f16.f16.f32 "
                 "{%0,%1,%2,%3}, {%4,%5,%6,%7}, {%8,%9,%10,%11}, {%0,%1,%2,%3}, %12, 0x0;"
                 : "+f"(c[0]), "+f"(c[1]), "+f"(c[2]), "+f"(c[3])
                 : "r"(a[0]), "r"(a[1]), "r"(a[2]), "r"(a[3]),
                   "r"(b[0]), "r"(b[1]), "r"(b[2]), "r"(b[3]), "r"(e));
}
__device__ __forceinline__ float pick6(uint32_t idx, float v0, float v1, float v2,
                                       float v3, float sl) {
    // idx: 0..3 -> v0..v3, 4 -> sl, 5 -> 0
    return (idx & 4u) ? ((idx & 1u) ? 0.0f : sl)
         : ((idx & 2u) ? ((idx & 1u) ? v3 : v2)
                       : ((idx & 1u) ? v1 : v0));
}

// ================= kernel 1: merged build — one block per token (A) / per row (W) =================
__global__ void __launch_bounds__(256) build_all_kernel(const float* __restrict__ x,
                                                        const float* __restrict__ grid,
                                                        const float* __restrict__ coeff,
                                                        const float* __restrict__ sb,
                                                        const float* __restrict__ ss) {
    __shared__ alignas(16) char shraw[18432];   // A-part: 14336 B, W-part: 18432 B
    const int t = threadIdx.x;

    if (blockIdx.x >= TOKENS) {
        // ---- W-part: one block per output row, SMEM-staged for full coalescing ----
        const int o = blockIdx.x - TOKENS;
        const float s = ss[0];
        float*  cin  = reinterpret_cast<float*>(shraw);            // 2816 floats (11264 B)
        float*  sbin = reinterpret_cast<float*>(shraw + 11264);    // 256 floats  (1024 B)
        __half* outb = reinterpret_cast<__half*>(shraw + 12288);   // 3072 halves (6144 B)
        __half* w = W2_buf + (size_t)o * KDE;
#pragma unroll 1
        for (int chunk = 0; chunk < 4; ++chunk) {
            const int cbase = chunk * 256;
            // coalesced load: coeff[o, cbase..cbase+255, :] = 2816 floats
            const float* csrc = coeff + ((size_t)o * IN_DIM + cbase) * GK;
            for (int j = t; j < 2816; j += 256) cin[j] = csrc[j];
            sbin[t] = sb[(size_t)o * IN_DIM + cbase + t];
            __syncthreads();
            // permute: thread t = channel cbase+t, 12 output slots
            const float* cc = cin + t * GK;       // stride 11: bank-conflict-free
            const float sv  = sbin[t];
            __half* oo = outb + t * 12;
#pragma unroll
            for (int p = 0; p < 12; ++p) {
                const int slt = PERM2[p];
                oo[p] = __float2half((slt >= 0) ? cc[slt] * s : sv);
            }
            __syncthreads();
            // coalesced writeback: 6144 B = 384 float4
            const float4* src4 = reinterpret_cast<const float4*>(outb);
            float4* dst4 = reinterpret_cast<float4*>(w + (size_t)cbase * 12);
            for (int j = t; j < 384; j += 256) dst4[j] = src4[j];
            __syncthreads();
        }
        return;
    }

    // ---- A-part: 4 channels per thread, coalesced float4 input ----
    __half2*  shv = reinterpret_cast<__half2*>(shraw);             // 12288 B
    uint16_t* shc = reinterpret_cast<uint16_t*>(shraw + 12288);    // 2048 B
    const int b = blockIdx.x;
    const float g0    = grid[0];
    const float inv_h = 1.0f / (grid[1] - grid[0]);
    const float4 x4 = reinterpret_cast<const float4*>(x + (size_t)b * IN_DIM)[t];
    const float xs[4] = {x4.x, x4.y, x4.z, x4.w};

#pragma unroll
    for (int c = 0; c < 4; ++c) {
        const int   ch = 4 * t + c;
        const float xv = xs[c];
        const float pos = (xv - g0) * inv_h;
        const int   j0  = (int)floorf(pos);
        const uint32_t jc = ((unsigned)j0 <= 13u) ? (uint32_t)j0 : 14u;

        const float u  = pos - (float)j0;
        const float u2 = u * u, u3 = u2 * u, om = 1.0f - u;
        const float c6 = 1.0f / 6.0f;
        const float v0 = om * om * om * c6;                    // slot j0-3
        const float v1 = (4.0f - 6.0f * u2 + 3.0f * u3) * c6;  // slot j0-2
        const float v2 = (1.0f + 3.0f * (u + u2 - u3)) * c6;   // slot j0-1
        const float v3 = u3 * c6;                              // slot j0
        const float sl = __fdividef(xv, 1.0f + __expf(-xv));   // silu

        const uint32_t sel = SEL_LUT[jc];
        shc[ch] = CODE_LUT[jc];
#pragma unroll
        for (int g = 0; g < 3; ++g) {
            const float q0 = pick6((sel >> (8 * g))     & 7u, v0, v1, v2, v3, sl);
            const float q1 = pick6((sel >> (8 * g + 4)) & 7u, v0, v1, v2, v3, sl);
            shv[ch * 3 + g] = __floats2half2_rn(q0, q1);
        }
    }

    __syncthreads();
    // coalesced value copy: 1024*3 half2 = 768 float4 -> 3 per thread
    __half* dst = A_sp + (size_t)b * CKC;
    const float4* src = reinterpret_cast<const float4*>(shv);
#pragma unroll
    for (int j = 0; j < 3; ++j)
        reinterpret_cast<float4*>(dst)[t + 256 * j] = src[t + 256 * j];

    // pack 1024 x 12-bit codes -> 384 uint32 metadata words (dense-k bitstream)
    for (int w = t; w < METAW; w += 256) {
        const int bit0 = 32 * w;
        const int c0   = bit0 / 12;
        const int d    = bit0 - 12 * c0;
        uint64_t acc = 0;
#pragma unroll
        for (int q = 0; q < 4; ++q) {
            const int ci = c0 + q;
            if (ci < IN_DIM) acc |= (uint64_t)shc[ci] << (12 * q);
        }
        Meta_buf[(size_t)b * METAW + w] = (uint32_t)(acc >> d);
    }
}

// ================= kernel 2: sparse HMMA GEMM, split-K=4, 2 CTAs/SM =================
__global__ void __launch_bounds__(256, 2) kan_spgemm_kernel() {
    extern __shared__ char smem[];
    const uint32_t sbase = smem_u32(smem);
    const int t    = threadIdx.x;
    const int lane = t & 31;
    const int wid  = t >> 5;
    const int m0   = blockIdx.y * TILE_M;
    const int n0   = blockIdx.x * TILE_N;
    const int wm   = (wid >> 2) * 64;
    const int wn   = (wid & 3) * 32;

    const __half*   Ag = A_sp     + (size_t)m0 * CKC   + (size_t)blockIdx.z * SEG_C;
    const __half*   Bg = W2_buf   + (size_t)n0 * KDE   + (size_t)blockIdx.z * SEG_DE;
    const uint32_t* Mg = Meta_buf + (size_t)m0 * METAW + (size_t)blockIdx.z * SEG_MW;

    float acc[4][4][4];
#pragma unroll
    for (int i = 0; i < 4; i++)
#pragma unroll
        for (int j = 0; j < 4; j++)
#pragma unroll
            for (int q = 0; q < 4; q++) acc[i][j][q] = 0.0f;

    // ---- prologue ----
#pragma unroll
    for (int s = 0; s < STAGES - 1; ++s) {
        const uint32_t ba = sbase + s * STG;
#pragma unroll
        for (int j = 0; j < 2; ++j) {                      // A: 512 chunks
            const int c = t + 256 * j, r = c >> 2, col = c & 3;
            cp_async16(ba + (uint32_t)(r * LDSA + col * 16),
                       Ag + (size_t)r * CKC + s * BKC + col * 8);
        }
#pragma unroll
        for (int q = 0; q < 4; ++q) {                      // B: 1024 chunks
            const int c = t + 256 * q, r = c >> 3, col = c & 7;
            cp_async16(ba + A_BYTES + (uint32_t)(r * LDSB + col * 16),
                       Bg + (size_t)r * KDE + s * BKD + col * 8);
        }
        if (t < TILE_M)
            cp_async8(ba + A_BYTES + B_BYTES + (uint32_t)(t * 8),
                      Mg + (size_t)t * METAW + s * 2);
        asm volatile("cp.async.commit_group;" ::: "memory");
    }

    // ---- main loop ----
    for (int it = 0; it < NITER_S; ++it) {
        asm volatile("cp.async.wait_group %0;" :: "n"(STAGES - 2) : "memory");
        __syncthreads();

        const int nit = it + STAGES - 1;
        if (nit < NITER_S) {
            const uint32_t ba = sbase + (nit % STAGES) * STG;
#pragma unroll
            for (int j = 0; j < 2; ++j) {
                const int c = t + 256 * j, r = c >> 2, col = c & 3;
                cp_async16(ba + (uint32_t)(r * LDSA + col * 16),
                           Ag + (size_t)r * CKC + nit * BKC + col * 8);
            }
#pragma unroll
            for (int q = 0; q < 4; ++q) {
                const int c = t + 256 * q, r = c >> 3, col = c & 7;
                cp_async16(ba + A_BYTES + (uint32_t)(r * LDSB + col * 16),
                           Bg + (size_t)r * KDE + nit * BKD + col * 8);
            }
            if (t < TILE_M)
                cp_async8(ba + A_BYTES + B_BYTES + (uint32_t)(t * 8),
                          Mg + (size_t)t * METAW + nit * 2);
        }
        asm volatile("cp.async.commit_group;" ::: "memory");

        // compute stage it
        const uint32_t ba   = sbase + (it % STAGES) * STG;
        const uint32_t boff = ba + A_BYTES;
        const uint32_t moff = boff + B_BYTES;
        // metadata (L2 distribution): lane 4q+s (s=lane&1) supplies, for k-half s:
        // low 16 bits = row q, high 16 bits = row q+8.
        const int q   = lane >> 2;
        const int msh = (lane & 1) * 16;
        uint32_t ek[4][2];
#pragma unroll
        for (int mt = 0; mt < 4; ++mt) {
            uint2 lo, hi;
            asm volatile("ld.shared.v2.b32 {%0,%1}, [%2];" : "=r"(lo.x), "=r"(lo.y)
                         : "r"(moff + (uint32_t)((wm + mt * 16 + q) * 8)));
            asm volatile("ld.shared.v2.b32 {%0,%1}, [%2];" : "=r"(hi.x), "=r"(hi.y)
                         : "r"(moff + (uint32_t)((wm + mt * 16 + q + 8) * 8)));
            ek[mt][0] = ((lo.x >> msh) & 0xFFFFu) | (((hi.x >> msh) & 0xFFFFu) << 16);
            ek[mt][1] = ((lo.y >> msh) & 0xFFFFu) | (((hi.y >> msh) & 0xFFFFu) << 16);
        }
#pragma unroll
        for (int ks = 0; ks < 2; ++ks) {
            uint32_t afr[4][4], bfr[4][4];
#pragma unroll
            for (int mt = 0; mt < 4; ++mt)
                ldmatrix_x4(afr[mt],
                    ba + (uint32_t)((wm + mt * 16 + (lane & 15)) * LDSA
                                    + ks * 32 + (lane >> 4) * 16));
#pragma unroll
            for (int nt = 0; nt < 4; ++nt)
                ldmatrix_x4(bfr[nt],
                    boff + (uint32_t)((wn + nt * 8 + (lane & 7)) * LDSB
                                      + ks * 64 + ((lane >> 3) & 3) * 16));
#pragma unroll
            for (int mt = 0; mt < 4; ++mt)
#pragma unroll
                for (int nt = 0; nt < 4; ++nt)
                    mma_sp(acc[mt][nt], afr[mt], bfr[nt], ek[mt][ks]);
        }
    }

    // ---- epilogue: fp16 partials -> Y4h ----
    __half* yp = Y4h_buf + (size_t)blockIdx.z * TOKENS * OUT_DIM;
    const int crow = lane >> 2, ccol = (lane & 3) * 2;
#pragma unroll
    for (int mt = 0; mt < 4; ++mt) {
        const int rbase = m0 + wm + mt * 16 + crow;
        __half* y0 = yp + (size_t)rbase * OUT_DIM + n0 + wn + ccol;
        __half* y1 = yp + (size_t)(rbase + 8) * OUT_DIM + n0 + wn + ccol;
#pragma unroll
        for (int nt = 0; nt < 4; ++nt) {
            *reinterpret_cast<__half2*>(y0 + nt * 8) =
                __floats2half2_rn(acc[mt][nt][0], acc[mt][nt][1]);
            *reinterpret_cast<__half2*>(y1 + nt * 8) =
                __floats2half2_rn(acc[mt][nt][2], acc[mt][nt][3]);
        }
    }
}

// ================= kernel 3: y = sum of 4 fp16 partials (fp32 accum) =================
__global__ void __launch_bounds__(256) reduce_kernel(float* __restrict__ y) {
    const size_t n8 = (size_t)TOKENS * OUT_DIM / 8;       // uint4 chunks (8 halves)
    const size_t i  = (size_t)blockIdx.x * 256 + threadIdx.x;
    const uint4* p = reinterpret_cast<const uint4*>(Y4h_buf);
    uint4 a = p[i], b = p[i + n8], c = p[i + 2 * n8], d = p[i + 3 * n8];
    float out[8];
#pragma unroll
    for (int j = 0; j < 4; ++j) {
        const float2 fa = __half22float2(reinterpret_cast<const __half2*>(&a)[j]);
        const float2 fb = __half22float2(reinterpret_cast<const __half2*>(&b)[j]);
        const float2 fc = __half22float2(reinterpret_cast<const __half2*>(&c)[j]);
        const float2 fd = __half22float2(reinterpret_cast<const __half2*>(&d)[j]);
        out[2 * j]     = (fa.x + fb.x) + (fc.x + fd.x);
        out[2 * j + 1] = (fa.y + fb.y) + (fc.y + fd.y);
    }
    float4* yo = reinterpret_cast<float4*>(y) + 2 * i;
    yo[0] = make_float4(out[0], out[1], out[2], out[3]);
    yo[1] = make_float4(out[4], out[5], out[6], out[7]);
}

// ================= host =================
extern "C" void kernel_launch(void* const* d_in, const int* in_sizes, int n_in,
                              void* d_out, int out_size) {
    const float* x     = (const float*)d_in[0];
    const float* grid  = (const float*)d_in[1];
    const float* coeff = (const float*)d_in[2];
    const float* sbase = (const float*)d_in[3];
    const float* sspl  = (const float*)d_in[4];
    float* y = (float*)d_out;

    cudaFuncSetAttribute(kan_spgemm_kernel,
                         cudaFuncAttributeMaxDynamicSharedMemorySize, SMEM_TOT);

    build_all_kernel<<<TOKENS + OUT_DIM, 256>>>(x, grid, coeff, sbase, sspl);
    kan_spgemm_kernel<<<dim3(OUT_DIM / TILE_N, TOKENS / TILE_M, KSPLIT), 256, SMEM_TOT>>>();
    reduce_kernel<<<(TOKENS * OUT_DIM / 8) / 256, 256>>>(y);
}